// round 1
// baseline (speedup 1.0000x reference)
#include <cuda_runtime.h>
#include <math.h>

// ---------------- problem constants ----------------
static constexpr int LAYERS = 32, HEADS = 8, SEQ = 1024, DIM = 128;
static constexpr int VOCAB = 128000, BEAM = 3, HIST = 16;

static constexpr long long KV_IN_ELEMS  = (long long)LAYERS * HEADS * SEQ * DIM;      // 33,554,432
static constexpr long long KV_OUT_ELEMS = KV_IN_ELEMS * BEAM;                          // 100,663,296

// output layout (flattened reference tuple, all as float32; int values numeric-cast)
static constexpr long long OFF_KV      = 0;
static constexpr long long OFF_TOPIDX  = KV_OUT_ELEMS;                                  // 3
static constexpr long long OFF_SAVEID  = OFF_TOPIDX + BEAM;                             // 51
static constexpr long long OFF_REPPEN  = OFF_SAVEID + (long long)BEAM * (HIST + 1);     // 384,000
static constexpr long long OFF_TOPPROB = OFF_REPPEN + (long long)BEAM * VOCAB;          // 3
static constexpr long long OFF_MAXIDX  = OFF_TOPPROB + BEAM;                            // 1

// ---------------- scratch (device globals; no allocation allowed) ----------------
static constexpr int NB1 = 64;   // phase-1 blocks
__device__ float g_m[NB1];
__device__ float g_s[NB1];
__device__ float g_tv[NB1 * 3];
__device__ int   g_ti[NB1 * 3];
__device__ int   g_topidx[BEAM];
__device__ float g_pen;

// ---------------- helpers ----------------
// insert (v,i) into descending top-3 list; tie-break lower index first (jax top_k order)
__device__ __forceinline__ void ins3(float v, int i, float tv[3], int ti[3]) {
    if (v > tv[0] || (v == tv[0] && i < ti[0])) {
        tv[2] = tv[1]; ti[2] = ti[1];
        tv[1] = tv[0]; ti[1] = ti[0];
        tv[0] = v;     ti[0] = i;
    } else if (v > tv[1] || (v == tv[1] && i < ti[1])) {
        tv[2] = tv[1]; ti[2] = ti[1];
        tv[1] = v;     ti[1] = i;
    } else if (v > tv[2] || (v == tv[2] && i < ti[2])) {
        tv[2] = v;     ti[2] = i;
    }
}

// merge other's (m,s) + top3 into mine (online softmax merge + top-3 merge)
__device__ __forceinline__ void merge_state(float& m, float& s, float tv[3], int ti[3],
                                            float om, float os,
                                            float ov0, float ov1, float ov2,
                                            int oi0, int oi1, int oi2) {
    float mm = fmaxf(m, om);
    s = s * __expf(m - mm) + os * __expf(om - mm);
    m = mm;
    ins3(ov0, oi0, tv, ti);
    ins3(ov1, oi1, tv, ti);
    ins3(ov2, oi2, tv, ti);
}

// ---------------- phase 1: per-block online softmax + top-3 ----------------
__global__ void __launch_bounds__(256) topk_phase1(const float* __restrict__ logits) {
    const int tid  = threadIdx.x;
    const int gtid = blockIdx.x * 256 + tid;
    const int lane = tid & 31;
    const int wid  = tid >> 5;

    float m = -INFINITY, s = 0.f;
    float tv[3] = {-INFINITY, -INFINITY, -INFINITY};
    int   ti[3] = {VOCAB, VOCAB, VOCAB};

    const float4* L4 = reinterpret_cast<const float4*>(logits);
    const int NV4 = VOCAB / 4;                     // 32000
    for (int j = gtid; j < NV4; j += NB1 * 256) {  // stride 16384 -> every thread gets >=1 elem
        float4 x = L4[j];
        float xs[4] = {x.x, x.y, x.z, x.w};
#pragma unroll
        for (int k = 0; k < 4; k++) {
            float v = xs[k];
            int   i = 4 * j + k;
            if (v > m) { s = s * __expf(m - v) + 1.f; m = v; }
            else       { s += __expf(v - m); }
            ins3(v, i, tv, ti);
        }
    }

    // warp reduce (guarded: lane+off<32 avoids self-merge duplication)
#pragma unroll
    for (int off = 16; off; off >>= 1) {
        float om  = __shfl_down_sync(0xffffffffu, m, off);
        float os  = __shfl_down_sync(0xffffffffu, s, off);
        float ov0 = __shfl_down_sync(0xffffffffu, tv[0], off);
        float ov1 = __shfl_down_sync(0xffffffffu, tv[1], off);
        float ov2 = __shfl_down_sync(0xffffffffu, tv[2], off);
        int   oi0 = __shfl_down_sync(0xffffffffu, ti[0], off);
        int   oi1 = __shfl_down_sync(0xffffffffu, ti[1], off);
        int   oi2 = __shfl_down_sync(0xffffffffu, ti[2], off);
        if (lane + off < 32)
            merge_state(m, s, tv, ti, om, os, ov0, ov1, ov2, oi0, oi1, oi2);
    }

    __shared__ float sm[8], ss[8], stv[8][3];
    __shared__ int   sti[8][3];
    if (lane == 0) {
        sm[wid] = m; ss[wid] = s;
        stv[wid][0] = tv[0]; stv[wid][1] = tv[1]; stv[wid][2] = tv[2];
        sti[wid][0] = ti[0]; sti[wid][1] = ti[1]; sti[wid][2] = ti[2];
    }
    __syncthreads();

    if (wid == 0 && lane < 8) {
        m = sm[lane]; s = ss[lane];
        tv[0] = stv[lane][0]; tv[1] = stv[lane][1]; tv[2] = stv[lane][2];
        ti[0] = sti[lane][0]; ti[1] = sti[lane][1]; ti[2] = sti[lane][2];
#pragma unroll
        for (int off = 4; off; off >>= 1) {
            float om  = __shfl_down_sync(0x000000ffu, m, off);
            float os  = __shfl_down_sync(0x000000ffu, s, off);
            float ov0 = __shfl_down_sync(0x000000ffu, tv[0], off);
            float ov1 = __shfl_down_sync(0x000000ffu, tv[1], off);
            float ov2 = __shfl_down_sync(0x000000ffu, tv[2], off);
            int   oi0 = __shfl_down_sync(0x000000ffu, ti[0], off);
            int   oi1 = __shfl_down_sync(0x000000ffu, ti[1], off);
            int   oi2 = __shfl_down_sync(0x000000ffu, ti[2], off);
            if (lane + off < 8)
                merge_state(m, s, tv, ti, om, os, ov0, ov1, ov2, oi0, oi1, oi2);
        }
        if (lane == 0) {
            g_m[blockIdx.x] = m;
            g_s[blockIdx.x] = s;
            g_tv[blockIdx.x * 3 + 0] = tv[0]; g_ti[blockIdx.x * 3 + 0] = ti[0];
            g_tv[blockIdx.x * 3 + 1] = tv[1]; g_ti[blockIdx.x * 3 + 1] = ti[1];
            g_tv[blockIdx.x * 3 + 2] = tv[2]; g_ti[blockIdx.x * 3 + 2] = ti[2];
        }
    }
}

// ---------------- phase 2: merge 64 partials; write small outputs ----------------
__global__ void __launch_bounds__(64) topk_phase2(const int* __restrict__ save_id,
                                                  const float* __restrict__ penval,
                                                  float* __restrict__ out) {
    const int tid = threadIdx.x;

    __shared__ float fin_m, fin_s, fin_tv[3];
    __shared__ int   fin_ti[3];

    if (tid < 32) {
        // each lane merges entries tid and tid+32
        float m = g_m[tid], s = g_s[tid];
        float tv[3] = {g_tv[tid * 3 + 0], g_tv[tid * 3 + 1], g_tv[tid * 3 + 2]};
        int   ti[3] = {g_ti[tid * 3 + 0], g_ti[tid * 3 + 1], g_ti[tid * 3 + 2]};
        int j = tid + 32;
        merge_state(m, s, tv, ti, g_m[j], g_s[j],
                    g_tv[j * 3 + 0], g_tv[j * 3 + 1], g_tv[j * 3 + 2],
                    g_ti[j * 3 + 0], g_ti[j * 3 + 1], g_ti[j * 3 + 2]);
#pragma unroll
        for (int off = 16; off; off >>= 1) {
            float om  = __shfl_down_sync(0xffffffffu, m, off);
            float os  = __shfl_down_sync(0xffffffffu, s, off);
            float ov0 = __shfl_down_sync(0xffffffffu, tv[0], off);
            float ov1 = __shfl_down_sync(0xffffffffu, tv[1], off);
            float ov2 = __shfl_down_sync(0xffffffffu, tv[2], off);
            int   oi0 = __shfl_down_sync(0xffffffffu, ti[0], off);
            int   oi1 = __shfl_down_sync(0xffffffffu, ti[1], off);
            int   oi2 = __shfl_down_sync(0xffffffffu, ti[2], off);
            if (tid + off < 32)
                merge_state(m, s, tv, ti, om, os, ov0, ov1, ov2, oi0, oi1, oi2);
        }
        if (tid == 0) {
            fin_m = m; fin_s = s;
            fin_tv[0] = tv[0]; fin_tv[1] = tv[1]; fin_tv[2] = tv[2];
            fin_ti[0] = ti[0]; fin_ti[1] = ti[1]; fin_ti[2] = ti[2];
        }
    }
    __syncthreads();

    const float logZ = fin_m + logf(fin_s);

    if (tid < BEAM) {
        out[OFF_TOPIDX  + tid] = (float)fin_ti[tid];
        out[OFF_TOPPROB + tid] = fin_tv[tid] - logZ;
        g_topidx[tid] = fin_ti[tid];
    }
    if (tid == 0) {
        out[OFF_MAXIDX] = (float)fin_ti[0];
        g_pen = penval[0];
    }
    if (tid < BEAM * (HIST + 1)) {   // 51 writes
        int r = tid / (HIST + 1);
        int c = tid % (HIST + 1);
        out[OFF_SAVEID + tid] = (c < HIST) ? (float)save_id[r * HIST + c]
                                           : (float)fin_ti[r];
    }
}

// ---------------- repeat-penalty copy (after phase 2) ----------------
__global__ void __launch_bounds__(256) rep_pen_kernel(const float* __restrict__ rp,
                                                      float* __restrict__ out) {
    int i = blockIdx.x * 256 + threadIdx.x;          // 0 .. 383,999
    if (i < BEAM * VOCAB) {
        int row = i / VOCAB;
        int col = i - row * VOCAB;
        float v = rp[i];
        if (col == g_topidx[row]) v *= g_pen;
        out[OFF_REPPEN + i] = v;
    }
}

// ---------------- KV tile: read 1 float4, write 3 (beam replicate) ----------------
__global__ void __launch_bounds__(256) kv_tile_kernel(const float4* __restrict__ in,
                                                      float4* __restrict__ out) {
    const unsigned INNER = (unsigned)(HEADS * SEQ * DIM) / 4;   // 262144 f4 per layer (2^18)
    unsigned idx = blockIdx.x * 256u + threadIdx.x;             // 0 .. 8,388,607 (exact)
    unsigned l = idx >> 18;
    unsigned r = idx & (INNER - 1);
    float4 v = in[idx];
    float4* o = out + (unsigned long long)l * 3u * INNER + r;
    o[0]         = v;
    o[INNER]     = v;
    o[2u * INNER] = v;
}

// ---------------- launch ----------------
extern "C" void kernel_launch(void* const* d_in, const int* in_sizes, int n_in,
                              void* d_out, int out_size) {
    const float* kv      = (const float*)d_in[0];
    const float* logits  = (const float*)d_in[1];
    const int*   save_id = (const int*)d_in[2];
    const float* reppen  = (const float*)d_in[3];
    const float* penval  = (const float*)d_in[4];
    float* out = (float*)d_out;

    topk_phase1<<<NB1, 256>>>(logits);
    topk_phase2<<<1, 64>>>(save_id, penval, out);
    rep_pen_kernel<<<(BEAM * VOCAB + 255) / 256, 256>>>(reppen, out);

    // 33,554,432 floats / 4 = 8,388,608 float4 = 32768 blocks * 256 threads exactly
    kv_tile_kernel<<<32768, 256>>>((const float4*)kv, (float4*)(out + OFF_KV));
}

// round 2
// speedup vs baseline: 1.1985x; 1.1985x over previous
#include <cuda_runtime.h>
#include <math.h>

// ---------------- problem constants ----------------
static constexpr int LAYERS = 32, HEADS = 8, SEQ = 1024, DIM = 128;
static constexpr int VOCAB = 128000, BEAM = 3, HIST = 16;

static constexpr long long KV_IN_ELEMS  = (long long)LAYERS * HEADS * SEQ * DIM;      // 33,554,432
static constexpr long long KV_OUT_ELEMS = KV_IN_ELEMS * BEAM;                          // 100,663,296

// output layout (flattened reference tuple, all as float32)
static constexpr long long OFF_KV      = 0;
static constexpr long long OFF_TOPIDX  = KV_OUT_ELEMS;
static constexpr long long OFF_SAVEID  = OFF_TOPIDX + BEAM;
static constexpr long long OFF_REPPEN  = OFF_SAVEID + (long long)BEAM * (HIST + 1);
static constexpr long long OFF_TOPPROB = OFF_REPPEN + (long long)BEAM * VOCAB;
static constexpr long long OFF_MAXIDX  = OFF_TOPPROB + BEAM;

// ---------------- scratch ----------------
static constexpr int NB1 = 64;   // phase-1 blocks
__device__ float g_m[NB1];
__device__ float g_s[NB1];
__device__ float g_tv[NB1 * 3];
__device__ int   g_ti[NB1 * 3];
__device__ int   g_topidx[BEAM];
__device__ float g_pen;
__device__ int   g_cnt = 0;

// ---------------- helpers ----------------
__device__ __forceinline__ void ins3(float v, int i, float tv[3], int ti[3]) {
    if (v > tv[0] || (v == tv[0] && i < ti[0])) {
        tv[2] = tv[1]; ti[2] = ti[1];
        tv[1] = tv[0]; ti[1] = ti[0];
        tv[0] = v;     ti[0] = i;
    } else if (v > tv[1] || (v == tv[1] && i < ti[1])) {
        tv[2] = tv[1]; ti[2] = ti[1];
        tv[1] = v;     ti[1] = i;
    } else if (v > tv[2] || (v == tv[2] && i < ti[2])) {
        tv[2] = v;     ti[2] = i;
    }
}

__device__ __forceinline__ void merge_state(float& m, float& s, float tv[3], int ti[3],
                                            float om, float os,
                                            float ov0, float ov1, float ov2,
                                            int oi0, int oi1, int oi2) {
    float mm = fmaxf(m, om);
    s = s * __expf(m - mm) + os * __expf(om - mm);
    m = mm;
    ins3(ov0, oi0, tv, ti);
    ins3(ov1, oi1, tv, ti);
    ins3(ov2, oi2, tv, ti);
}

#define WARP_MERGE(MASK, LIMIT, OFF)                                           \
    {                                                                          \
        float om  = __shfl_down_sync(MASK, m, OFF);                            \
        float os  = __shfl_down_sync(MASK, s, OFF);                            \
        float ov0 = __shfl_down_sync(MASK, tv[0], OFF);                        \
        float ov1 = __shfl_down_sync(MASK, tv[1], OFF);                        \
        float ov2 = __shfl_down_sync(MASK, tv[2], OFF);                        \
        int   oi0 = __shfl_down_sync(MASK, ti[0], OFF);                        \
        int   oi1 = __shfl_down_sync(MASK, ti[1], OFF);                        \
        int   oi2 = __shfl_down_sync(MASK, ti[2], OFF);                        \
        if (lane + OFF < LIMIT)                                                \
            merge_state(m, s, tv, ti, om, os, ov0, ov1, ov2, oi0, oi1, oi2);   \
    }

// ---------------- launch 1: topk (phase1 + last-block phase2) ----------------
__global__ void __launch_bounds__(256) topk_kernel(const float* __restrict__ logits,
                                                   const int* __restrict__ save_id,
                                                   const float* __restrict__ penval,
                                                   float* __restrict__ out) {
    const int tid  = threadIdx.x;
    const int gtid = blockIdx.x * 256 + tid;
    const int lane = tid & 31;
    const int wid  = tid >> 5;

    float m = -INFINITY, s = 0.f;
    float tv[3] = {-INFINITY, -INFINITY, -INFINITY};
    int   ti[3] = {VOCAB, VOCAB, VOCAB};

    const float4* L4 = reinterpret_cast<const float4*>(logits);
    const int NV4 = VOCAB / 4;
    for (int j = gtid; j < NV4; j += NB1 * 256) {
        float4 x = L4[j];
        float xs[4] = {x.x, x.y, x.z, x.w};
#pragma unroll
        for (int k = 0; k < 4; k++) {
            float v = xs[k];
            int   i = 4 * j + k;
            if (v > m) { s = s * __expf(m - v) + 1.f; m = v; }
            else       { s += __expf(v - m); }
            ins3(v, i, tv, ti);
        }
    }

    WARP_MERGE(0xffffffffu, 32, 16)
    WARP_MERGE(0xffffffffu, 32, 8)
    WARP_MERGE(0xffffffffu, 32, 4)
    WARP_MERGE(0xffffffffu, 32, 2)
    WARP_MERGE(0xffffffffu, 32, 1)

    __shared__ float sm[8], ss[8], stv[8][3];
    __shared__ int   sti[8][3];
    if (lane == 0) {
        sm[wid] = m; ss[wid] = s;
        stv[wid][0] = tv[0]; stv[wid][1] = tv[1]; stv[wid][2] = tv[2];
        sti[wid][0] = ti[0]; sti[wid][1] = ti[1]; sti[wid][2] = ti[2];
    }
    __syncthreads();

    if (wid == 0 && lane < 8) {
        m = sm[lane]; s = ss[lane];
        tv[0] = stv[lane][0]; tv[1] = stv[lane][1]; tv[2] = stv[lane][2];
        ti[0] = sti[lane][0]; ti[1] = sti[lane][1]; ti[2] = sti[lane][2];
        WARP_MERGE(0x000000ffu, 8, 4)
        WARP_MERGE(0x000000ffu, 8, 2)
        WARP_MERGE(0x000000ffu, 8, 1)
        if (lane == 0) {
            g_m[blockIdx.x] = m;
            g_s[blockIdx.x] = s;
            g_tv[blockIdx.x * 3 + 0] = tv[0]; g_ti[blockIdx.x * 3 + 0] = ti[0];
            g_tv[blockIdx.x * 3 + 1] = tv[1]; g_ti[blockIdx.x * 3 + 1] = ti[1];
            g_tv[blockIdx.x * 3 + 2] = tv[2]; g_ti[blockIdx.x * 3 + 2] = ti[2];
        }
    }

    // ---- last-block ticket: the final block performs phase 2 ----
    __shared__ bool amLast;
    __threadfence();
    if (tid == 0) {
        int prev = atomicAdd(&g_cnt, 1);
        amLast = (prev == NB1 - 1);
        if (amLast) g_cnt = 0;            // reset for next launch
    }
    __syncthreads();
    if (!amLast) return;

    // phase 2 (threads 0..31 merge 64 partials)
    __shared__ float fin_m, fin_s, fin_tv[3];
    __shared__ int   fin_ti[3];
    if (tid < 32) {
        float m2 = g_m[tid], s2 = g_s[tid];
        float tv2[3] = {g_tv[tid * 3 + 0], g_tv[tid * 3 + 1], g_tv[tid * 3 + 2]};
        int   ti2[3] = {g_ti[tid * 3 + 0], g_ti[tid * 3 + 1], g_ti[tid * 3 + 2]};
        {
            int j = tid + 32;
            merge_state(m2, s2, tv2, ti2, g_m[j], g_s[j],
                        g_tv[j * 3 + 0], g_tv[j * 3 + 1], g_tv[j * 3 + 2],
                        g_ti[j * 3 + 0], g_ti[j * 3 + 1], g_ti[j * 3 + 2]);
        }
        // reuse WARP_MERGE with aliased names
        float m = m2, s = s2;
        float tv[3] = {tv2[0], tv2[1], tv2[2]};
        int   ti[3] = {ti2[0], ti2[1], ti2[2]};
        int lane = tid;
        WARP_MERGE(0xffffffffu, 32, 16)
        WARP_MERGE(0xffffffffu, 32, 8)
        WARP_MERGE(0xffffffffu, 32, 4)
        WARP_MERGE(0xffffffffu, 32, 2)
        WARP_MERGE(0xffffffffu, 32, 1)
        if (tid == 0) {
            fin_m = m; fin_s = s;
            fin_tv[0] = tv[0]; fin_tv[1] = tv[1]; fin_tv[2] = tv[2];
            fin_ti[0] = ti[0]; fin_ti[1] = ti[1]; fin_ti[2] = ti[2];
        }
    }
    __syncthreads();

    const float logZ = fin_m + logf(fin_s);

    if (tid < BEAM) {
        out[OFF_TOPIDX  + tid] = (float)fin_ti[tid];
        out[OFF_TOPPROB + tid] = fin_tv[tid] - logZ;
        g_topidx[tid] = fin_ti[tid];
    }
    if (tid == 0) {
        out[OFF_MAXIDX] = (float)fin_ti[0];
        g_pen = penval[0];
    }
    if (tid < BEAM * (HIST + 1)) {
        int r = tid / (HIST + 1);
        int c = tid % (HIST + 1);
        out[OFF_SAVEID + tid] = (c < HIST) ? (float)save_id[r * HIST + c]
                                           : (float)fin_ti[r];
    }
}

// ---------------- launch 2: fused KV tile + repeat-penalty ----------------
static constexpr int KV_BLOCKS = 16384;                       // 2 float4 per thread
static constexpr int RP_BLOCKS = (BEAM * VOCAB + 255) / 256;  // 1500

__global__ void __launch_bounds__(256) kv_rp_kernel(const float4* __restrict__ in,
                                                    const float* __restrict__ rp,
                                                    float* __restrict__ outf) {
    const int tid = threadIdx.x;

    if (blockIdx.x < KV_BLOCKS) {
        // KV replicate: each thread handles 2 independent float4 (MLP=2)
        const unsigned INNER = (unsigned)(HEADS * SEQ * DIM) / 4;   // 262144 (2^18)
        float4* out = reinterpret_cast<float4*>(outf + OFF_KV);
        unsigned base = blockIdx.x * 512u + (unsigned)tid;          // chunk of 512 f4, layer-aligned
        unsigned i0 = base, i1 = base + 256u;

        float4 v0 = __ldcs(in + i0);
        float4 v1 = __ldcs(in + i1);

        unsigned l  = i0 >> 18;                                     // same layer for both
        unsigned r0 = i0 & (INNER - 1);
        unsigned r1 = i1 & (INNER - 1);
        float4* o = out + (unsigned long long)l * 3u * INNER;
        __stcs(o + r0,              v0);
        __stcs(o + r1,              v1);
        __stcs(o + INNER + r0,      v0);
        __stcs(o + INNER + r1,      v1);
        __stcs(o + 2u * INNER + r0, v0);
        __stcs(o + 2u * INNER + r1, v1);
    } else {
        // repeat-penalty copy (g_topidx / g_pen written by previous launch)
        int i = (blockIdx.x - KV_BLOCKS) * 256 + tid;
        if (i < BEAM * VOCAB) {
            int row = i / VOCAB;
            int col = i - row * VOCAB;
            float v = rp[i];
            if (col == g_topidx[row]) v *= g_pen;
            outf[OFF_REPPEN + i] = v;
        }
    }
}

// ---------------- launch ----------------
extern "C" void kernel_launch(void* const* d_in, const int* in_sizes, int n_in,
                              void* d_out, int out_size) {
    const float* kv      = (const float*)d_in[0];
    const float* logits  = (const float*)d_in[1];
    const int*   save_id = (const int*)d_in[2];
    const float* reppen  = (const float*)d_in[3];
    const float* penval  = (const float*)d_in[4];
    float* out = (float*)d_out;

    topk_kernel<<<NB1, 256>>>(logits, save_id, penval, out);
    kv_rp_kernel<<<KV_BLOCKS + RP_BLOCKS, 256>>>((const float4*)kv, reppen, out);
}

// round 3
// speedup vs baseline: 1.2841x; 1.0714x over previous
#include <cuda_runtime.h>
#include <math.h>

// ---------------- problem constants ----------------
static constexpr int LAYERS = 32, HEADS = 8, SEQ = 1024, DIM = 128;
static constexpr int VOCAB = 128000, BEAM = 3, HIST = 16;

static constexpr long long KV_IN_ELEMS  = (long long)LAYERS * HEADS * SEQ * DIM;      // 33,554,432
static constexpr long long KV_OUT_ELEMS = KV_IN_ELEMS * BEAM;                          // 100,663,296

// output layout (flattened reference tuple, all as float32)
static constexpr long long OFF_KV      = 0;
static constexpr long long OFF_TOPIDX  = KV_OUT_ELEMS;
static constexpr long long OFF_SAVEID  = OFF_TOPIDX + BEAM;
static constexpr long long OFF_REPPEN  = OFF_SAVEID + (long long)BEAM * (HIST + 1);
static constexpr long long OFF_TOPPROB = OFF_REPPEN + (long long)BEAM * VOCAB;
static constexpr long long OFF_MAXIDX  = OFF_TOPPROB + BEAM;

// ---------------- grid layout (single kernel) ----------------
static constexpr int NB1       = 64;                                   // topk blocks
static constexpr int KV_BLOCKS = 8192;                                 // 4 float4 / thread
static constexpr int RP_BLOCKS = (BEAM * VOCAB + 255) / 256;           // 1500
static constexpr int KV_END    = NB1 + KV_BLOCKS;
static constexpr int GRID      = KV_END + RP_BLOCKS;

// ---------------- scratch ----------------
__device__ float g_m[NB1];
__device__ float g_s[NB1];
__device__ float g_tv[NB1 * 3];
__device__ int   g_ti[NB1 * 3];
__device__ int   g_topidx[BEAM];
__device__ float g_pen;
__device__ int   g_cnt = 0;      // topk ticket
__device__ int   g_flag = 0;     // topk-done release flag
__device__ int   g_rp_done = 0;  // rp completion counter (resets flag)

// ---------------- helpers ----------------
__device__ __forceinline__ void ins3(float v, int i, float tv[3], int ti[3]) {
    if (v > tv[0] || (v == tv[0] && i < ti[0])) {
        tv[2] = tv[1]; ti[2] = ti[1];
        tv[1] = tv[0]; ti[1] = ti[0];
        tv[0] = v;     ti[0] = i;
    } else if (v > tv[1] || (v == tv[1] && i < ti[1])) {
        tv[2] = tv[1]; ti[2] = ti[1];
        tv[1] = v;     ti[1] = i;
    } else if (v > tv[2] || (v == tv[2] && i < ti[2])) {
        tv[2] = v;     ti[2] = i;
    }
}

__device__ __forceinline__ void merge_state(float& m, float& s, float tv[3], int ti[3],
                                            float om, float os,
                                            float ov0, float ov1, float ov2,
                                            int oi0, int oi1, int oi2) {
    float mm = fmaxf(m, om);
    s = s * __expf(m - mm) + os * __expf(om - mm);
    m = mm;
    ins3(ov0, oi0, tv, ti);
    ins3(ov1, oi1, tv, ti);
    ins3(ov2, oi2, tv, ti);
}

#define WARP_MERGE(MASK, LIMIT, OFF)                                           \
    {                                                                          \
        float om  = __shfl_down_sync(MASK, m, OFF);                            \
        float os  = __shfl_down_sync(MASK, s, OFF);                            \
        float ov0 = __shfl_down_sync(MASK, tv[0], OFF);                        \
        float ov1 = __shfl_down_sync(MASK, tv[1], OFF);                        \
        float ov2 = __shfl_down_sync(MASK, tv[2], OFF);                        \
        int   oi0 = __shfl_down_sync(MASK, ti[0], OFF);                        \
        int   oi1 = __shfl_down_sync(MASK, ti[1], OFF);                        \
        int   oi2 = __shfl_down_sync(MASK, ti[2], OFF);                        \
        if (lane + OFF < LIMIT)                                                \
            merge_state(m, s, tv, ti, om, os, ov0, ov1, ov2, oi0, oi1, oi2);   \
    }

// ---------------- topk role (blocks 0..63) ----------------
__device__ void topk_role(int bid,
                          const float* __restrict__ logits,
                          const int* __restrict__ save_id,
                          const float* __restrict__ penval,
                          float* __restrict__ out) {
    const int tid  = threadIdx.x;
    const int gtid = bid * 256 + tid;
    const int lane = tid & 31;
    const int wid  = tid >> 5;

    float m = -INFINITY, s = 0.f;
    float tv[3] = {-INFINITY, -INFINITY, -INFINITY};
    int   ti[3] = {VOCAB, VOCAB, VOCAB};

    const float4* L4 = reinterpret_cast<const float4*>(logits);
    const int NV4 = VOCAB / 4;
    for (int j = gtid; j < NV4; j += NB1 * 256) {
        float4 x = L4[j];
        float xs[4] = {x.x, x.y, x.z, x.w};
#pragma unroll
        for (int k = 0; k < 4; k++) {
            float v = xs[k];
            int   i = 4 * j + k;
            if (v > m) { s = s * __expf(m - v) + 1.f; m = v; }
            else       { s += __expf(v - m); }
            ins3(v, i, tv, ti);
        }
    }

    WARP_MERGE(0xffffffffu, 32, 16)
    WARP_MERGE(0xffffffffu, 32, 8)
    WARP_MERGE(0xffffffffu, 32, 4)
    WARP_MERGE(0xffffffffu, 32, 2)
    WARP_MERGE(0xffffffffu, 32, 1)

    __shared__ float sm[8], ss[8], stv[8][3];
    __shared__ int   sti[8][3];
    if (lane == 0) {
        sm[wid] = m; ss[wid] = s;
        stv[wid][0] = tv[0]; stv[wid][1] = tv[1]; stv[wid][2] = tv[2];
        sti[wid][0] = ti[0]; sti[wid][1] = ti[1]; sti[wid][2] = ti[2];
    }
    __syncthreads();

    if (wid == 0 && lane < 8) {
        m = sm[lane]; s = ss[lane];
        tv[0] = stv[lane][0]; tv[1] = stv[lane][1]; tv[2] = stv[lane][2];
        ti[0] = sti[lane][0]; ti[1] = sti[lane][1]; ti[2] = sti[lane][2];
        WARP_MERGE(0x000000ffu, 8, 4)
        WARP_MERGE(0x000000ffu, 8, 2)
        WARP_MERGE(0x000000ffu, 8, 1)
        if (lane == 0) {
            g_m[bid] = m;
            g_s[bid] = s;
            g_tv[bid * 3 + 0] = tv[0]; g_ti[bid * 3 + 0] = ti[0];
            g_tv[bid * 3 + 1] = tv[1]; g_ti[bid * 3 + 1] = ti[1];
            g_tv[bid * 3 + 2] = tv[2]; g_ti[bid * 3 + 2] = ti[2];
        }
    }

    // last-block ticket
    __shared__ bool amLast;
    __threadfence();
    if (tid == 0) {
        int prev = atomicAdd(&g_cnt, 1);
        amLast = (prev == NB1 - 1);
        if (amLast) g_cnt = 0;
    }
    __syncthreads();
    if (!amLast) return;

    // final merge of 64 partials
    __shared__ float fin_m, fin_s, fin_tv[3];
    __shared__ int   fin_ti[3];
    if (tid < 32) {
        float m2 = g_m[tid], s2 = g_s[tid];
        float tv2[3] = {g_tv[tid * 3 + 0], g_tv[tid * 3 + 1], g_tv[tid * 3 + 2]};
        int   ti2[3] = {g_ti[tid * 3 + 0], g_ti[tid * 3 + 1], g_ti[tid * 3 + 2]};
        {
            int j = tid + 32;
            merge_state(m2, s2, tv2, ti2, g_m[j], g_s[j],
                        g_tv[j * 3 + 0], g_tv[j * 3 + 1], g_tv[j * 3 + 2],
                        g_ti[j * 3 + 0], g_ti[j * 3 + 1], g_ti[j * 3 + 2]);
        }
        float m = m2, s = s2;
        float tv[3] = {tv2[0], tv2[1], tv2[2]};
        int   ti[3] = {ti2[0], ti2[1], ti2[2]};
        int lane = tid;
        WARP_MERGE(0xffffffffu, 32, 16)
        WARP_MERGE(0xffffffffu, 32, 8)
        WARP_MERGE(0xffffffffu, 32, 4)
        WARP_MERGE(0xffffffffu, 32, 2)
        WARP_MERGE(0xffffffffu, 32, 1)
        if (tid == 0) {
            fin_m = m; fin_s = s;
            fin_tv[0] = tv[0]; fin_tv[1] = tv[1]; fin_tv[2] = tv[2];
            fin_ti[0] = ti[0]; fin_ti[1] = ti[1]; fin_ti[2] = ti[2];
        }
    }
    __syncthreads();

    const float logZ = fin_m + logf(fin_s);

    if (tid < BEAM) {
        out[OFF_TOPIDX  + tid] = (float)fin_ti[tid];
        out[OFF_TOPPROB + tid] = fin_tv[tid] - logZ;
        g_topidx[tid] = fin_ti[tid];
    }
    if (tid == 0) g_pen = penval[0];
    if (tid == 0) out[OFF_MAXIDX] = (float)fin_ti[0];
    if (tid < BEAM * (HIST + 1)) {
        int r = tid / (HIST + 1);
        int c = tid % (HIST + 1);
        out[OFF_SAVEID + tid] = (c < HIST) ? (float)save_id[r * HIST + c]
                                           : (float)fin_ti[r];
    }

    // release: publish topk results to rp blocks
    __threadfence();
    __syncthreads();
    if (tid == 0) *((volatile int*)&g_flag) = 1;
}

// ---------------- single fused kernel ----------------
__global__ void __launch_bounds__(256) fused_kernel(const float4* __restrict__ kv,
                                                    const float* __restrict__ logits,
                                                    const int* __restrict__ save_id,
                                                    const float* __restrict__ rp,
                                                    const float* __restrict__ penval,
                                                    float* __restrict__ outf) {
    const int bid = blockIdx.x;
    const int tid = threadIdx.x;

    if (bid < NB1) {
        topk_role(bid, logits, save_id, penval, outf);
        return;
    }

    if (bid < KV_END) {
        // ---- KV replicate: 4 independent float4 per thread (MLP=4) ----
        const unsigned INNER = (unsigned)(HEADS * SEQ * DIM) / 4;   // 262144 (2^18)
        float4* out = reinterpret_cast<float4*>(outf + OFF_KV);
        unsigned base = (unsigned)(bid - NB1) * 1024u + (unsigned)tid;  // 1024 f4/block, layer-aligned

        float4 v0 = __ldcs(kv + base);
        float4 v1 = __ldcs(kv + base + 256u);
        float4 v2 = __ldcs(kv + base + 512u);
        float4 v3 = __ldcs(kv + base + 768u);

        unsigned l = base >> 18;                 // all 4 in same layer (1024 | 262144)
        unsigned r = base & (INNER - 1);
        float4* o = out + (unsigned long long)l * 3u * INNER + r;
#pragma unroll
        for (int b = 0; b < 3; b++) {
            __stcs(o,        v0);
            __stcs(o + 256,  v1);
            __stcs(o + 512,  v2);
            __stcs(o + 768,  v3);
            o += INNER;
        }
        return;
    }

    // ---- repeat-penalty role (last 1500 blocks; waits on topk flag) ----
    if (tid == 0) {
        while (*((volatile int*)&g_flag) == 0) { __nanosleep(64); }
    }
    __syncthreads();
    __threadfence();   // order subsequent global reads after flag observation

    int i = (bid - KV_END) * 256 + tid;
    if (i < BEAM * VOCAB) {
        int row = i / VOCAB;
        int col = i - row * VOCAB;
        float v = rp[i];
        int t = *((volatile int*)&g_topidx[row]);
        if (col == t) v *= *((volatile float*)&g_pen);
        outf[OFF_REPPEN + i] = v;
    }

    // completion ticket: last rp block resets flag for next graph replay
    __threadfence();
    __syncthreads();
    if (tid == 0) {
        int prev = atomicAdd(&g_rp_done, 1);
        if (prev == RP_BLOCKS - 1) {
            g_rp_done = 0;
            g_flag = 0;
        }
    }
}

// ---------------- launch ----------------
extern "C" void kernel_launch(void* const* d_in, const int* in_sizes, int n_in,
                              void* d_out, int out_size) {
    const float* kv      = (const float*)d_in[0];
    const float* logits  = (const float*)d_in[1];
    const int*   save_id = (const int*)d_in[2];
    const float* reppen  = (const float*)d_in[3];
    const float* penval  = (const float*)d_in[4];
    float* out = (float*)d_out;

    fused_kernel<<<GRID, 256>>>((const float4*)kv, logits, save_id, reppen, penval, out);
}

// round 4
// speedup vs baseline: 1.2884x; 1.0033x over previous
#include <cuda_runtime.h>
#include <math.h>

// ---------------- problem constants ----------------
static constexpr int LAYERS = 32, HEADS = 8, SEQ = 1024, DIM = 128;
static constexpr int VOCAB = 128000, BEAM = 3, HIST = 16;

static constexpr long long KV_IN_ELEMS  = (long long)LAYERS * HEADS * SEQ * DIM;      // 33,554,432
static constexpr long long KV_OUT_ELEMS = KV_IN_ELEMS * BEAM;                          // 100,663,296

// output layout (flattened reference tuple, all as float32)
static constexpr long long OFF_KV      = 0;
static constexpr long long OFF_TOPIDX  = KV_OUT_ELEMS;
static constexpr long long OFF_SAVEID  = OFF_TOPIDX + BEAM;
static constexpr long long OFF_REPPEN  = OFF_SAVEID + (long long)BEAM * (HIST + 1);
static constexpr long long OFF_TOPPROB = OFF_REPPEN + (long long)BEAM * VOCAB;
static constexpr long long OFF_MAXIDX  = OFF_TOPPROB + BEAM;

// ---------------- grid layout (single kernel) ----------------
static constexpr int NB1       = 64;                                   // topk blocks
static constexpr int KV_BLOCKS = 16384;                                // 2 float4 / thread (R2-best geometry)
static constexpr int RP_BLOCKS = (BEAM * VOCAB + 255) / 256;           // 1500
static constexpr int KV_END    = NB1 + KV_BLOCKS;
static constexpr int GRID      = KV_END + RP_BLOCKS;

// ---------------- scratch ----------------
__device__ float g_m[NB1];
__device__ float g_s[NB1];
__device__ float g_tv[NB1 * 3];
__device__ int   g_ti[NB1 * 3];
__device__ int   g_topidx[BEAM];
__device__ float g_pen;
__device__ int   g_cnt = 0;      // topk ticket
__device__ int   g_flag = 0;     // topk-done release flag
__device__ int   g_rp_done = 0;  // rp completion counter

// ---------------- helpers ----------------
__device__ __forceinline__ void ins3(float v, int i, float tv[3], int ti[3]) {
    if (v > tv[0] || (v == tv[0] && i < ti[0])) {
        tv[2] = tv[1]; ti[2] = ti[1];
        tv[1] = tv[0]; ti[1] = ti[0];
        tv[0] = v;     ti[0] = i;
    } else if (v > tv[1] || (v == tv[1] && i < ti[1])) {
        tv[2] = tv[1]; ti[2] = ti[1];
        tv[1] = v;     ti[1] = i;
    } else if (v > tv[2] || (v == tv[2] && i < ti[2])) {
        tv[2] = v;     ti[2] = i;
    }
}

__device__ __forceinline__ void merge_state(float& m, float& s, float tv[3], int ti[3],
                                            float om, float os,
                                            float ov0, float ov1, float ov2,
                                            int oi0, int oi1, int oi2) {
    float mm = fmaxf(m, om);
    s = s * __expf(m - mm) + os * __expf(om - mm);
    m = mm;
    ins3(ov0, oi0, tv, ti);
    ins3(ov1, oi1, tv, ti);
    ins3(ov2, oi2, tv, ti);
}

#define WARP_MERGE(MASK, LIMIT, OFF)                                           \
    {                                                                          \
        float om  = __shfl_down_sync(MASK, m, OFF);                            \
        float os  = __shfl_down_sync(MASK, s, OFF);                            \
        float ov0 = __shfl_down_sync(MASK, tv[0], OFF);                        \
        float ov1 = __shfl_down_sync(MASK, tv[1], OFF);                        \
        float ov2 = __shfl_down_sync(MASK, tv[2], OFF);                        \
        int   oi0 = __shfl_down_sync(MASK, ti[0], OFF);                        \
        int   oi1 = __shfl_down_sync(MASK, ti[1], OFF);                        \
        int   oi2 = __shfl_down_sync(MASK, ti[2], OFF);                        \
        if (lane + OFF < LIMIT)                                                \
            merge_state(m, s, tv, ti, om, os, ov0, ov1, ov2, oi0, oi1, oi2);   \
    }

// ---------------- topk role (blocks 0..63) ----------------
__device__ void topk_role(int bid,
                          const float* __restrict__ logits,
                          const int* __restrict__ save_id,
                          const float* __restrict__ penval,
                          float* __restrict__ out) {
    const int tid  = threadIdx.x;
    const int gtid = bid * 256 + tid;
    const int lane = tid & 31;
    const int wid  = tid >> 5;

    float m = -INFINITY, s = 0.f;
    float tv[3] = {-INFINITY, -INFINITY, -INFINITY};
    int   ti[3] = {VOCAB, VOCAB, VOCAB};

    const float4* L4 = reinterpret_cast<const float4*>(logits);
    const int NV4 = VOCAB / 4;
    for (int j = gtid; j < NV4; j += NB1 * 256) {
        float4 x = L4[j];
        float xs[4] = {x.x, x.y, x.z, x.w};
#pragma unroll
        for (int k = 0; k < 4; k++) {
            float v = xs[k];
            int   i = 4 * j + k;
            if (v > m) { s = s * __expf(m - v) + 1.f; m = v; }
            else       { s += __expf(v - m); }
            ins3(v, i, tv, ti);
        }
    }

    WARP_MERGE(0xffffffffu, 32, 16)
    WARP_MERGE(0xffffffffu, 32, 8)
    WARP_MERGE(0xffffffffu, 32, 4)
    WARP_MERGE(0xffffffffu, 32, 2)
    WARP_MERGE(0xffffffffu, 32, 1)

    __shared__ float sm[8], ss[8], stv[8][3];
    __shared__ int   sti[8][3];
    if (lane == 0) {
        sm[wid] = m; ss[wid] = s;
        stv[wid][0] = tv[0]; stv[wid][1] = tv[1]; stv[wid][2] = tv[2];
        sti[wid][0] = ti[0]; sti[wid][1] = ti[1]; sti[wid][2] = ti[2];
    }
    __syncthreads();

    if (wid == 0 && lane < 8) {
        m = sm[lane]; s = ss[lane];
        tv[0] = stv[lane][0]; tv[1] = stv[lane][1]; tv[2] = stv[lane][2];
        ti[0] = sti[lane][0]; ti[1] = sti[lane][1]; ti[2] = sti[lane][2];
        WARP_MERGE(0x000000ffu, 8, 4)
        WARP_MERGE(0x000000ffu, 8, 2)
        WARP_MERGE(0x000000ffu, 8, 1)
        if (lane == 0) {
            g_m[bid] = m;
            g_s[bid] = s;
            g_tv[bid * 3 + 0] = tv[0]; g_ti[bid * 3 + 0] = ti[0];
            g_tv[bid * 3 + 1] = tv[1]; g_ti[bid * 3 + 1] = ti[1];
            g_tv[bid * 3 + 2] = tv[2]; g_ti[bid * 3 + 2] = ti[2];
        }
    }

    // last-block ticket
    __shared__ bool amLast;
    __threadfence();
    if (tid == 0) {
        int prev = atomicAdd(&g_cnt, 1);
        amLast = (prev == NB1 - 1);
        if (amLast) g_cnt = 0;
    }
    __syncthreads();
    if (!amLast) return;

    // final merge of 64 partials
    __shared__ float fin_m, fin_s, fin_tv[3];
    __shared__ int   fin_ti[3];
    if (tid < 32) {
        float m2 = g_m[tid], s2 = g_s[tid];
        float tv2[3] = {g_tv[tid * 3 + 0], g_tv[tid * 3 + 1], g_tv[tid * 3 + 2]};
        int   ti2[3] = {g_ti[tid * 3 + 0], g_ti[tid * 3 + 1], g_ti[tid * 3 + 2]};
        {
            int j = tid + 32;
            merge_state(m2, s2, tv2, ti2, g_m[j], g_s[j],
                        g_tv[j * 3 + 0], g_tv[j * 3 + 1], g_tv[j * 3 + 2],
                        g_ti[j * 3 + 0], g_ti[j * 3 + 1], g_ti[j * 3 + 2]);
        }
        float m = m2, s = s2;
        float tv[3] = {tv2[0], tv2[1], tv2[2]};
        int   ti[3] = {ti2[0], ti2[1], ti2[2]};
        int lane = tid;
        WARP_MERGE(0xffffffffu, 32, 16)
        WARP_MERGE(0xffffffffu, 32, 8)
        WARP_MERGE(0xffffffffu, 32, 4)
        WARP_MERGE(0xffffffffu, 32, 2)
        WARP_MERGE(0xffffffffu, 32, 1)
        if (tid == 0) {
            fin_m = m; fin_s = s;
            fin_tv[0] = tv[0]; fin_tv[1] = tv[1]; fin_tv[2] = tv[2];
            fin_ti[0] = ti[0]; fin_ti[1] = ti[1]; fin_ti[2] = ti[2];
        }
    }
    __syncthreads();

    const float logZ = fin_m + logf(fin_s);

    if (tid < BEAM) {
        out[OFF_TOPIDX  + tid] = (float)fin_ti[tid];
        out[OFF_TOPPROB + tid] = fin_tv[tid] - logZ;
        g_topidx[tid] = fin_ti[tid];
    }
    if (tid == 0) g_pen = penval[0];
    if (tid == 0) out[OFF_MAXIDX] = (float)fin_ti[0];
    if (tid < BEAM * (HIST + 1)) {
        int r = tid / (HIST + 1);
        int c = tid % (HIST + 1);
        out[OFF_SAVEID + tid] = (c < HIST) ? (float)save_id[r * HIST + c]
                                           : (float)fin_ti[r];
    }

    // publish topk results
    __threadfence();
    __syncthreads();
    if (tid == 0) *((volatile int*)&g_flag) = 1;
}

// ---------------- single fused kernel ----------------
__global__ void __launch_bounds__(256) fused_kernel(const float4* __restrict__ kv,
                                                    const float* __restrict__ logits,
                                                    const int* __restrict__ save_id,
                                                    const float* __restrict__ rp,
                                                    const float* __restrict__ penval,
                                                    float* __restrict__ outf) {
    const int bid = blockIdx.x;
    const int tid = threadIdx.x;

    if (bid < NB1) {
        topk_role(bid, logits, save_id, penval, outf);
        return;
    }

    if (bid < KV_END) {
        // ---- KV replicate: 2 independent float4 per thread (R2-measured-best) ----
        const unsigned INNER = (unsigned)(HEADS * SEQ * DIM) / 4;   // 262144 (2^18)
        float4* out = reinterpret_cast<float4*>(outf + OFF_KV);
        unsigned base = (unsigned)(bid - NB1) * 512u + (unsigned)tid;  // 512 f4/block, layer-aligned
        unsigned i0 = base, i1 = base + 256u;

        float4 v0 = __ldcs(kv + i0);
        float4 v1 = __ldcs(kv + i1);

        unsigned l  = i0 >> 18;                                     // same layer for both
        unsigned r0 = i0 & (INNER - 1);
        unsigned r1 = i1 & (INNER - 1);
        float4* o = out + (unsigned long long)l * 3u * INNER;
        __stcs(o + r0,              v0);
        __stcs(o + r1,              v1);
        __stcs(o + INNER + r0,      v0);
        __stcs(o + INNER + r1,      v1);
        __stcs(o + 2u * INNER + r0, v0);
        __stcs(o + 2u * INNER + r1, v1);
        return;
    }

    // ---- repeat-penalty role: unconditional copy (NO dependency on topk) ----
    int i = (bid - KV_END) * 256 + tid;
    if (i < BEAM * VOCAB) {
        outf[OFF_REPPEN + i] = rp[i];
    }

    // completion ticket: last rp block applies the 3-element penalty fixup
    __threadfence();
    __syncthreads();
    if (tid == 0) {
        int prev = atomicAdd(&g_rp_done, 1);
        if (prev == RP_BLOCKS - 1) {
            g_rp_done = 0;
            // wait for topk results (long since published in practice)
            while (*((volatile int*)&g_flag) == 0) { __nanosleep(64); }
            __threadfence();
            float pen = *((volatile float*)&g_pen);
#pragma unroll
            for (int r = 0; r < BEAM; r++) {
                int t = *((volatile int*)&g_topidx[r]);
                outf[OFF_REPPEN + (long long)r * VOCAB + t] = rp[(long long)r * VOCAB + t] * pen;
            }
            __threadfence();
            g_flag = 0;   // reset for next graph replay
        }
    }
}

// ---------------- launch ----------------
extern "C" void kernel_launch(void* const* d_in, const int* in_sizes, int n_in,
                              void* d_out, int out_size) {
    const float* kv      = (const float*)d_in[0];
    const float* logits  = (const float*)d_in[1];
    const int*   save_id = (const int*)d_in[2];
    const float* reppen  = (const float*)d_in[3];
    const float* penval  = (const float*)d_in[4];
    float* out = (float*)d_out;

    fused_kernel<<<GRID, 256>>>((const float4*)kv, logits, save_id, reppen, penval, out);
}